// round 5
// baseline (speedup 1.0000x reference)
#include <cuda_runtime.h>
#include <cuda_bf16.h>
#include <math.h>
#include <stdint.h>

#define N_TOK 8192
#define D_DIM 1024
#define E_NUM 8
#define H_DIM 4096
#define CAP   8192
#define PAIRS 16384

#define TM 128
#define TN 128
#define TK 64            // int8 elems per k-chunk (64 bytes per row)
#define ROWB 80          // padded SMEM row bytes (64 data + 16 pad)
#define AQ1 0
#define AQ0 10240
#define BQ1 20480
#define BQ0 30720
#define STG 40960
#define NSTAGE 4
#define GEMM_SMEM (NSTAGE * STG)
#define QMAX 16256.0f    // 127 * 128

// ---------------- device scratch ----------------
__device__ int   g_cnt[E_NUM];
__device__ int   g_off[E_NUM];
__device__ int   g_tok[E_NUM * CAP];
__device__ int   g_tslot[2 * N_TOK];
__device__ float g_tw  [2 * N_TOK];

__device__ int8_t g_xq1[(size_t)N_TOK * D_DIM];
__device__ int8_t g_xq0[(size_t)N_TOK * D_DIM];
__device__ float  g_xs [N_TOK];
__device__ float  g_hf [(size_t)PAIRS * H_DIM];     // fp32 hidden
__device__ int8_t g_hq1[(size_t)PAIRS * H_DIM];
__device__ int8_t g_hq0[(size_t)PAIRS * H_DIM];
__device__ float  g_hs [PAIRS];
__device__ float  g_y  [(size_t)PAIRS * D_DIM];
// packed weights, [E][N][K] int8 (transposed from [E][K][N] fp32)
__device__ int8_t g_B1q1[(size_t)E_NUM * H_DIM * D_DIM];
__device__ int8_t g_B1q0[(size_t)E_NUM * H_DIM * D_DIM];
__device__ float  g_B1s [E_NUM * H_DIM];
__device__ int8_t g_B2q1[(size_t)E_NUM * D_DIM * H_DIM];
__device__ int8_t g_B2q0[(size_t)E_NUM * D_DIM * H_DIM];
__device__ float  g_B2s [E_NUM * D_DIM];

// ---------------- helpers ----------------
__device__ __forceinline__ uint32_t smem_u32(const void* p) {
    return (uint32_t)__cvta_generic_to_shared(p);
}
#define CP16(dst, src) \
    asm volatile("cp.async.cg.shared.global [%0], [%1], 16;" :: "r"(dst), "l"(src) : "memory")
#define CP_COMMIT() asm volatile("cp.async.commit_group;" ::: "memory")

__device__ __forceinline__ void ldsm4(uint32_t* r, uint32_t addr) {
    asm volatile("ldmatrix.sync.aligned.m8n8.x4.shared.b16 {%0,%1,%2,%3}, [%4];"
        : "=r"(r[0]), "=r"(r[1]), "=r"(r[2]), "=r"(r[3]) : "r"(addr));
}
__device__ __forceinline__ void mma_s8(int* c, const uint32_t* a, const uint32_t* b) {
    asm volatile("mma.sync.aligned.m16n8k32.row.col.s32.s8.s8.s32 "
        "{%0,%1,%2,%3}, {%4,%5,%6,%7}, {%8,%9}, {%0,%1,%2,%3};"
        : "+r"(c[0]), "+r"(c[1]), "+r"(c[2]), "+r"(c[3])
        : "r"(a[0]), "r"(a[1]), "r"(a[2]), "r"(a[3]), "r"(b[0]), "r"(b[1]));
}
// v ~= S * (128*q1 + q0), inv = 1/S
__device__ __forceinline__ void quant2(float v, float inv, int8_t& q1, int8_t& q0) {
    float q  = v * inv;
    float f1 = rintf(q * 0.0078125f);
    float f0 = rintf(q - 128.0f * f1);
    q1 = (int8_t)(int)f1;
    q0 = (int8_t)(int)f0;
}

// ---------------- small kernels ----------------
__global__ void zero_cnt_kernel() {
    if (threadIdx.x < E_NUM) g_cnt[threadIdx.x] = 0;
}

// one block per token: row amax + two-level int8 quantization
__global__ __launch_bounds__(256) void cvt_x_kernel(const float* __restrict__ x) {
    const int t = blockIdx.x, tid = threadIdx.x;
    const float4 v = *(const float4*)(x + (size_t)t * D_DIM + tid * 4);
    float m = fmaxf(fmaxf(fabsf(v.x), fabsf(v.y)), fmaxf(fabsf(v.z), fabsf(v.w)));
    __shared__ float red[8];
    __shared__ float s_amax;
#pragma unroll
    for (int o = 16; o > 0; o >>= 1) m = fmaxf(m, __shfl_xor_sync(0xffffffffu, m, o));
    if ((tid & 31) == 0) red[tid >> 5] = m;
    __syncthreads();
    if (tid == 0) {
        float a = red[0];
#pragma unroll
        for (int i = 1; i < 8; i++) a = fmaxf(a, red[i]);
        s_amax = a;
        g_xs[t] = a / QMAX;
    }
    __syncthreads();
    const float inv = s_amax > 0.f ? QMAX / s_amax : 0.f;
    int8_t q1[4], q0[4];
#pragma unroll
    for (int i = 0; i < 4; i++)
        quant2(((const float*)&v)[i], inv, q1[i], q0[i]);
    *(char4*)(g_xq1 + (size_t)t * D_DIM + tid * 4) = make_char4(q1[0], q1[1], q1[2], q1[3]);
    *(char4*)(g_xq0 + (size_t)t * D_DIM + tid * 4) = make_char4(q0[0], q0[1], q0[2], q0[3]);
}

// one block per hidden row (4096 elems)
__global__ __launch_bounds__(256) void hquant_kernel() {
    const int r = blockIdx.x, tid = threadIdx.x;
    const float* row = g_hf + (size_t)r * H_DIM;
    float4 v[4];
    float m = 0.f;
#pragma unroll
    for (int i = 0; i < 4; i++) {
        v[i] = *(const float4*)(row + tid * 16 + i * 4);
        m = fmaxf(m, fmaxf(fmaxf(fabsf(v[i].x), fabsf(v[i].y)),
                           fmaxf(fabsf(v[i].z), fabsf(v[i].w))));
    }
    __shared__ float red[8];
    __shared__ float s_amax;
#pragma unroll
    for (int o = 16; o > 0; o >>= 1) m = fmaxf(m, __shfl_xor_sync(0xffffffffu, m, o));
    if ((tid & 31) == 0) red[tid >> 5] = m;
    __syncthreads();
    if (tid == 0) {
        float a = red[0];
#pragma unroll
        for (int i = 1; i < 8; i++) a = fmaxf(a, red[i]);
        s_amax = a;
        g_hs[r] = a / QMAX;
    }
    __syncthreads();
    const float inv = s_amax > 0.f ? QMAX / s_amax : 0.f;
#pragma unroll
    for (int i = 0; i < 4; i++) {
        int8_t q1[4], q0[4];
#pragma unroll
        for (int j = 0; j < 4; j++)
            quant2(((const float*)&v[i])[j], inv, q1[j], q0[j]);
        size_t o = (size_t)r * H_DIM + tid * 16 + i * 4;
        *(char4*)(g_hq1 + o) = make_char4(q1[0], q1[1], q1[2], q1[3]);
        *(char4*)(g_hq0 + o) = make_char4(q0[0], q0[1], q0[2], q0[3]);
    }
}

// per-output-neuron amax over K: W[e][K][N] -> S[e][N]
__global__ void wscale_kernel(const float* __restrict__ W, float* __restrict__ S,
                              int K, int N) {
    const int n = blockIdx.x * 256 + threadIdx.x;
    const int e = blockIdx.y;
    const float* p = W + (size_t)e * K * N + n;
    float m = 0.f;
    for (int k = 0; k < K; k++) m = fmaxf(m, fabsf(p[(size_t)k * N]));
    S[e * N + n] = m / QMAX;
}

// W[e][K][N] fp32 -> P[e][N][K] int8 two-level (32x32 tile transpose)
__global__ __launch_bounds__(256)
void pack_w_kernel(const float* __restrict__ W, const float* __restrict__ S,
                   int8_t* __restrict__ P1, int8_t* __restrict__ P0, int K, int N) {
    __shared__ float s[32][33];
    const int k0 = blockIdx.x * 32, n0 = blockIdx.y * 32, e = blockIdx.z;
    const int tid = threadIdx.x;
    const int kk = tid >> 5, nn = tid & 31;
#pragma unroll
    for (int i = 0; i < 4; i++)
        s[kk + i * 8][nn] = W[((size_t)e * K + k0 + kk + i * 8) * N + n0 + nn];
    __syncthreads();
    const int n_r = tid >> 4;
    const int kp  = (tid & 15) * 2;
#pragma unroll
    for (int i = 0; i < 2; i++) {
        int nr = n_r + i * 16;
        float Sv  = S[e * N + n0 + nr];
        float inv = Sv > 0.f ? 1.f / Sv : 0.f;
        int8_t a1, a0, b1, b0;
        quant2(s[kp][nr],     inv, a1, a0);
        quant2(s[kp + 1][nr], inv, b1, b0);
        size_t o = ((size_t)e * N + n0 + nr) * K + k0 + kp;
        *(char2*)(P1 + o) = make_char2(a1, b1);
        *(char2*)(P0 + o) = make_char2(a0, b0);
    }
}

__global__ void router_kernel(const float* __restrict__ x,
                              const float* __restrict__ Wr,
                              const float* __restrict__ br) {
    int warp = (blockIdx.x * blockDim.x + threadIdx.x) >> 5;
    int lane = threadIdx.x & 31;
    if (warp >= N_TOK) return;
    const float* xr = x + (size_t)warp * D_DIM;
    float acc[8];
#pragma unroll
    for (int e = 0; e < 8; e++) acc[e] = 0.0f;
    for (int d = lane; d < D_DIM; d += 32) {
        float xv = xr[d];
        const float4* w4 = (const float4*)(Wr + (size_t)d * E_NUM);
        float4 a = w4[0], b = w4[1];
        acc[0] += xv * a.x; acc[1] += xv * a.y; acc[2] += xv * a.z; acc[3] += xv * a.w;
        acc[4] += xv * b.x; acc[5] += xv * b.y; acc[6] += xv * b.z; acc[7] += xv * b.w;
    }
#pragma unroll
    for (int off = 16; off > 0; off >>= 1)
#pragma unroll
        for (int e = 0; e < 8; e++)
            acc[e] += __shfl_down_sync(0xffffffffu, acc[e], off);
    if (lane == 0) {
        float lg[8];
#pragma unroll
        for (int e = 0; e < 8; e++) lg[e] = acc[e] + br[e];
        int e0 = 0;
#pragma unroll
        for (int e = 1; e < 8; e++) if (lg[e] > lg[e0]) e0 = e;
        int e1 = (e0 == 0) ? 1 : 0;
#pragma unroll
        for (int e = 0; e < 8; e++)
            if (e != e0 && e != e1 && lg[e] > lg[e1]) e1 = e;
        float z  = __expf(lg[e1] - lg[e0]);
        float w0 = 1.0f / (1.0f + z);
        float w1 = z * w0;
        int p0 = atomicAdd(&g_cnt[e0], 1);
        g_tok[e0 * CAP + p0] = warp;
        int p1 = atomicAdd(&g_cnt[e1], 1);
        g_tok[e1 * CAP + p1] = warp;
        g_tslot[2 * warp]     = e0 * CAP + p0;  g_tw[2 * warp]     = w0;
        g_tslot[2 * warp + 1] = e1 * CAP + p1;  g_tw[2 * warp + 1] = w1;
    }
}

__global__ void offsets_kernel() {
    if (threadIdx.x == 0 && blockIdx.x == 0) {
        int acc = 0;
#pragma unroll
        for (int e = 0; e < E_NUM; e++) { g_off[e] = acc; acc += g_cnt[e]; }
    }
}

__global__ void combine_kernel(float* __restrict__ out) {
    int i = blockIdx.x * blockDim.x + threadIdx.x;
    int t = i >> 8;
    int j = (i & 255) << 2;
    int s0e = g_tslot[2 * t], s1e = g_tslot[2 * t + 1];
    float w0 = g_tw[2 * t], w1 = g_tw[2 * t + 1];
    size_t s0 = (size_t)g_off[s0e >> 13] + (s0e & (CAP - 1));
    size_t s1 = (size_t)g_off[s1e >> 13] + (s1e & (CAP - 1));
    float4 a = *(const float4*)(g_y + s0 * D_DIM + j);
    float4 b = *(const float4*)(g_y + s1 * D_DIM + j);
    float4 o;
    o.x = w0 * a.x + w1 * b.x;
    o.y = w0 * a.y + w1 * b.y;
    o.z = w0 * a.z + w1 * b.z;
    o.w = w0 * a.w + w1 * b.w;
    *(float4*)(out + (size_t)t * D_DIM + j) = o;
}

// ------------- grouped GEMM via mma.sync s8 (IMMA), two-level split -------------
template <int PHASE, int KDIM, int NDIM>
__global__ __launch_bounds__(256, 1)
void moe_imma(const int8_t* __restrict__ Aq1, const int8_t* __restrict__ Aq0,
              const float* __restrict__ Ascale,
              const int8_t* __restrict__ Bq1, const int8_t* __restrict__ Bq0,
              const float* __restrict__ Bscale,
              const float* __restrict__ bias) {
    constexpr int C = KDIM / TK;
    const int e  = blockIdx.z;
    const int Ne = g_cnt[e];
    const int m0 = blockIdx.x * TM;
    if (m0 >= Ne) return;
    const int n0 = blockIdx.y * TN;
    const int base = g_off[e];

    extern __shared__ __align__(128) char smem[];
    const uint32_t sb = smem_u32(smem);
    const int tid = threadIdx.x;

    // ---- load assignments: thread -> rows (tid>>2, +64), 16B seg (tid&3) ----
    const int r0 = tid >> 2;
    const int sg = (tid & 3) * 16;
    const char *a0q1, *a0q0, *a1q1, *a1q0;
    {
        int rr0 = min(m0 + r0, Ne - 1);
        int rr1 = min(m0 + r0 + 64, Ne - 1);
        size_t i0 = (PHASE == 1) ? (size_t)g_tok[e * CAP + rr0] : (size_t)(base + rr0);
        size_t i1 = (PHASE == 1) ? (size_t)g_tok[e * CAP + rr1] : (size_t)(base + rr1);
        a0q1 = (const char*)(Aq1 + i0 * KDIM) + sg;
        a0q0 = (const char*)(Aq0 + i0 * KDIM) + sg;
        a1q1 = (const char*)(Aq1 + i1 * KDIM) + sg;
        a1q0 = (const char*)(Aq0 + i1 * KDIM) + sg;
    }
    const size_t brow = (size_t)e * NDIM + n0 + r0;
    const char* b0q1 = (const char*)(Bq1 + brow * KDIM) + sg;
    const char* b0q0 = (const char*)(Bq0 + brow * KDIM) + sg;
    const char* b1q1 = b0q1 + (size_t)64 * KDIM;
    const char* b1q0 = b0q0 + (size_t)64 * KDIM;
    const uint32_t d0 = (uint32_t)r0 * ROWB + sg;
    const uint32_t d1 = d0 + 64 * ROWB;

    auto issue = [&](int c) {
        if (c < C) {
            uint32_t st = sb + (uint32_t)(c & (NSTAGE - 1)) * STG;
            int cb = c * TK;   // bytes per chunk along K
            CP16(st + AQ1 + d0, a0q1 + cb); CP16(st + AQ1 + d1, a1q1 + cb);
            CP16(st + AQ0 + d0, a0q0 + cb); CP16(st + AQ0 + d1, a1q0 + cb);
            CP16(st + BQ1 + d0, b0q1 + cb); CP16(st + BQ1 + d1, b1q1 + cb);
            CP16(st + BQ0 + d0, b0q0 + cb); CP16(st + BQ0 + d1, b1q0 + cb);
        }
        CP_COMMIT();
    };

    int acch[4][4][4], accm[4][4][4];
#pragma unroll
    for (int i = 0; i < 4; i++)
#pragma unroll
        for (int j = 0; j < 4; j++)
#pragma unroll
            for (int k = 0; k < 4; k++) { acch[i][j][k] = 0; accm[i][j][k] = 0; }

    const int lane = tid & 31, wid = tid >> 5;
    const int wm = (wid & 1) * 64;
    const int wn = (wid >> 1) * 32;
    const uint32_t a_off = (uint32_t)(wm + (lane & 15)) * ROWB + (lane >> 4) * 16;
    const uint32_t b_off = (uint32_t)(wn + (lane & 7) + ((lane >> 4) & 1) * 8) * ROWB
                         + ((lane >> 3) & 1) * 16;

    issue(0);
    issue(1);
    issue(2);

    for (int c = 0; c < C; c++) {
        asm volatile("cp.async.wait_group 2;" ::: "memory");
        __syncthreads();
        issue(c + 3);

        const uint32_t st = sb + (uint32_t)(c & (NSTAGE - 1)) * STG;
#pragma unroll
        for (int kk = 0; kk < 2; kk++) {
            uint32_t aq1[16], aq0[16], bq1[8], bq0[8];
#pragma unroll
            for (int tm = 0; tm < 4; tm++) {
                ldsm4(aq1 + tm * 4, st + AQ1 + a_off + tm * 16 * ROWB + kk * 32);
                ldsm4(aq0 + tm * 4, st + AQ0 + a_off + tm * 16 * ROWB + kk * 32);
            }
            ldsm4(bq1,     st + BQ1 + b_off + kk * 32);
            ldsm4(bq1 + 4, st + BQ1 + b_off + 16 * ROWB + kk * 32);
            ldsm4(bq0,     st + BQ0 + b_off + kk * 32);
            ldsm4(bq0 + 4, st + BQ0 + b_off + 16 * ROWB + kk * 32);
#pragma unroll
            for (int tm = 0; tm < 4; tm++)
#pragma unroll
                for (int tn = 0; tn < 4; tn++) {
                    mma_s8(acch[tm][tn], aq1 + tm * 4, bq1 + tn * 2);
                    mma_s8(accm[tm][tn], aq1 + tm * 4, bq0 + tn * 2);
                    mma_s8(accm[tm][tn], aq0 + tm * 4, bq1 + tn * 2);
                }
        }
    }

    // ---- epilogue: v = Sa*Sb*(16384*Chi + 128*Cmid) + bias ----
    const int lr_base  = wm + (lane >> 2);
    const int col_base = n0 + wn + 2 * (lane & 3);
    const float* bp = bias + (size_t)e * NDIM;
    const float* bs = Bscale + (size_t)e * NDIM;
#pragma unroll
    for (int tm = 0; tm < 4; tm++) {
#pragma unroll
        for (int half = 0; half < 2; half++) {
            int gr = m0 + lr_base + tm * 16 + half * 8;
            if (gr < Ne) {
                size_t pr = (size_t)(base + gr);
                float sa = (PHASE == 1) ? __ldg(Ascale + g_tok[e * CAP + gr])
                                        : __ldg(Ascale + pr);
#pragma unroll
                for (int tn = 0; tn < 4; tn++) {
                    int col = col_base + tn * 8;
                    float d0 = 16384.f * (float)acch[tm][tn][half * 2 + 0]
                             +   128.f * (float)accm[tm][tn][half * 2 + 0];
                    float d1 = 16384.f * (float)acch[tm][tn][half * 2 + 1]
                             +   128.f * (float)accm[tm][tn][half * 2 + 1];
                    float v0 = sa * __ldg(bs + col)     * d0 + __ldg(bp + col);
                    float v1 = sa * __ldg(bs + col + 1) * d1 + __ldg(bp + col + 1);
                    if (PHASE == 1) {
                        float2 o;
                        o.x = fmaxf(v0, 0.f);
                        o.y = fmaxf(v1, 0.f);
                        *(float2*)(g_hf + pr * H_DIM + col) = o;
                    } else {
                        float2 o; o.x = v0; o.y = v1;
                        *(float2*)(g_y + pr * D_DIM + col) = o;
                    }
                }
            }
        }
    }
}

// ---------------- launch ----------------
extern "C" void kernel_launch(void* const* d_in, const int* in_sizes, int n_in,
                              void* d_out, int out_size) {
    const float* x  = (const float*)d_in[0];
    const float* Wr = (const float*)d_in[1];
    const float* br = (const float*)d_in[2];
    const float* W1 = (const float*)d_in[3];
    const float* b1 = (const float*)d_in[4];
    const float* W2 = (const float*)d_in[5];
    const float* b2 = (const float*)d_in[6];
    float* out = (float*)d_out;

    cudaFuncSetAttribute(moe_imma<1, D_DIM, H_DIM>,
                         cudaFuncAttributeMaxDynamicSharedMemorySize, GEMM_SMEM);
    cudaFuncSetAttribute(moe_imma<2, H_DIM, D_DIM>,
                         cudaFuncAttributeMaxDynamicSharedMemorySize, GEMM_SMEM);

    int8_t *xq1, *xq0, *hq1, *hq0, *B1q1, *B1q0, *B2q1, *B2q0;
    float  *xs, *hs, *B1s, *B2s;
    cudaGetSymbolAddress((void**)&xq1, g_xq1);   cudaGetSymbolAddress((void**)&xq0, g_xq0);
    cudaGetSymbolAddress((void**)&xs,  g_xs);
    cudaGetSymbolAddress((void**)&hq1, g_hq1);   cudaGetSymbolAddress((void**)&hq0, g_hq0);
    cudaGetSymbolAddress((void**)&hs,  g_hs);
    cudaGetSymbolAddress((void**)&B1q1, g_B1q1); cudaGetSymbolAddress((void**)&B1q0, g_B1q0);
    cudaGetSymbolAddress((void**)&B1s,  g_B1s);
    cudaGetSymbolAddress((void**)&B2q1, g_B2q1); cudaGetSymbolAddress((void**)&B2q0, g_B2q0);
    cudaGetSymbolAddress((void**)&B2s,  g_B2s);

    zero_cnt_kernel<<<1, 32>>>();
    cvt_x_kernel<<<N_TOK, 256>>>(x);
    wscale_kernel<<<dim3(H_DIM / 256, E_NUM), 256>>>(W1, B1s, D_DIM, H_DIM);
    wscale_kernel<<<dim3(D_DIM / 256, E_NUM), 256>>>(W2, B2s, H_DIM, D_DIM);
    {
        dim3 g(D_DIM / 32, H_DIM / 32, E_NUM);
        pack_w_kernel<<<g, 256>>>(W1, B1s, B1q1, B1q0, D_DIM, H_DIM);
    }
    {
        dim3 g(H_DIM / 32, D_DIM / 32, E_NUM);
        pack_w_kernel<<<g, 256>>>(W2, B2s, B2q1, B2q0, H_DIM, D_DIM);
    }
    router_kernel<<<(N_TOK * 32 + 255) / 256, 256>>>(x, Wr, br);
    offsets_kernel<<<1, 32>>>();

    {   // GEMM1: gathered x [Ne,1024] @ W1 -> relu -> g_hf (fp32)
        dim3 g(CAP / TM, H_DIM / TN, E_NUM);
        moe_imma<1, D_DIM, H_DIM><<<g, 256, GEMM_SMEM>>>(xq1, xq0, xs, B1q1, B1q0, B1s, b1);
    }
    hquant_kernel<<<PAIRS, 256>>>();
    {   // GEMM2: h [Ne,4096] @ W2 -> g_y (+b2)
        dim3 g(CAP / TM, D_DIM / TN, E_NUM);
        moe_imma<2, H_DIM, D_DIM><<<g, 256, GEMM_SMEM>>>(hq1, hq0, hs, B2q1, B2q0, B2s, b2);
    }
    combine_kernel<<<N_TOK, 256>>>(out);
}

// round 6
// speedup vs baseline: 2.7083x; 2.7083x over previous
#include <cuda_runtime.h>
#include <cuda_bf16.h>
#include <math.h>
#include <stdint.h>

#define N_TOK 8192
#define D_DIM 1024
#define E_NUM 8
#define H_DIM 4096
#define CAP   8192
#define PAIRS 16384

#define TM 128
#define TN 256
#define TK 32            // bf16 elems per k-chunk (64 bytes per row)
#define ROWB 80          // padded SMEM row bytes (64 data + 16 pad)
#define AH 0
#define AL 10240
#define BH 20480
#define BL 40960
#define STG 61440
#define NSTAGE 3
#define GEMM_SMEM (NSTAGE * STG)

// ---------------- device scratch ----------------
__device__ int   g_cnt[E_NUM];
__device__ int   g_off[E_NUM];
__device__ int   g_tok[E_NUM * CAP];
__device__ int   g_tslot[2 * N_TOK];   // e*CAP + p for each token's 2 experts
__device__ float g_tw  [2 * N_TOK];

__device__ __nv_bfloat16 g_xh[(size_t)N_TOK * D_DIM];
__device__ __nv_bfloat16 g_xl[(size_t)N_TOK * D_DIM];
__device__ __nv_bfloat16 g_hh[(size_t)PAIRS * H_DIM];
__device__ __nv_bfloat16 g_hl[(size_t)PAIRS * H_DIM];
__device__ float         g_y [(size_t)PAIRS * D_DIM];
// packed weights, [E][N][K] row-major bf16 (transposed from [E][K][N] fp32)
__device__ __nv_bfloat16 g_B1h[(size_t)E_NUM * H_DIM * D_DIM];
__device__ __nv_bfloat16 g_B1l[(size_t)E_NUM * H_DIM * D_DIM];
__device__ __nv_bfloat16 g_B2h[(size_t)E_NUM * D_DIM * H_DIM];
__device__ __nv_bfloat16 g_B2l[(size_t)E_NUM * D_DIM * H_DIM];

// ---------------- helpers ----------------
__device__ __forceinline__ uint32_t smem_u32(const void* p) {
    return (uint32_t)__cvta_generic_to_shared(p);
}
#define CP16(dst, src) \
    asm volatile("cp.async.cg.shared.global [%0], [%1], 16;" :: "r"(dst), "l"(src) : "memory")
#define CP_COMMIT() asm volatile("cp.async.commit_group;" ::: "memory")

__device__ __forceinline__ void ldsm4(uint32_t* r, uint32_t addr) {
    asm volatile("ldmatrix.sync.aligned.m8n8.x4.shared.b16 {%0,%1,%2,%3}, [%4];"
        : "=r"(r[0]), "=r"(r[1]), "=r"(r[2]), "=r"(r[3]) : "r"(addr));
}
__device__ __forceinline__ void mma_bf16(float* c, const uint32_t* a, const uint32_t* b) {
    asm volatile("mma.sync.aligned.m16n8k16.row.col.f32.bf16.bf16.f32 "
        "{%0,%1,%2,%3}, {%4,%5,%6,%7}, {%8,%9}, {%0,%1,%2,%3};"
        : "+f"(c[0]), "+f"(c[1]), "+f"(c[2]), "+f"(c[3])
        : "r"(a[0]), "r"(a[1]), "r"(a[2]), "r"(a[3]), "r"(b[0]), "r"(b[1]));
}

// ---------------- small kernels ----------------
__global__ void zero_cnt_kernel() {
    if (threadIdx.x < E_NUM) g_cnt[threadIdx.x] = 0;
}

__global__ void cvt_x_kernel(const float* __restrict__ x) {
    size_t stride = (size_t)gridDim.x * blockDim.x;
    size_t n = (size_t)N_TOK * D_DIM;
    for (size_t i = (size_t)blockIdx.x * blockDim.x + threadIdx.x; i < n; i += stride) {
        float v = x[i];
        __nv_bfloat16 h = __float2bfloat16(v);
        g_xh[i] = h;
        g_xl[i] = __float2bfloat16(v - __bfloat162float(h));
    }
}

// W[e][K][N] fp32 -> P[e][N][K] bf16 hi/lo (32x32 tile transpose)
__global__ __launch_bounds__(256)
void pack_w_kernel(const float* __restrict__ W, __nv_bfloat16* __restrict__ Ph,
                   __nv_bfloat16* __restrict__ Pl, int K, int N) {
    __shared__ float s[32][33];
    const int k0 = blockIdx.x * 32, n0 = blockIdx.y * 32, e = blockIdx.z;
    const int tid = threadIdx.x;
    const int kk = tid >> 5, nn = tid & 31;
#pragma unroll
    for (int i = 0; i < 4; i++)
        s[kk + i * 8][nn] = W[((size_t)e * K + k0 + kk + i * 8) * N + n0 + nn];
    __syncthreads();
    const int n_r = tid >> 4;          // 0..15
    const int kp  = (tid & 15) * 2;
#pragma unroll
    for (int i = 0; i < 2; i++) {
        int nr = n_r + i * 16;
        float v0 = s[kp][nr], v1 = s[kp + 1][nr];
        __nv_bfloat16 h0 = __float2bfloat16(v0), h1 = __float2bfloat16(v1);
        __nv_bfloat162 hp; hp.x = h0; hp.y = h1;
        __nv_bfloat162 lp;
        lp.x = __float2bfloat16(v0 - __bfloat162float(h0));
        lp.y = __float2bfloat16(v1 - __bfloat162float(h1));
        size_t o = ((size_t)e * N + n0 + nr) * K + k0 + kp;
        *(__nv_bfloat162*)(Ph + o) = hp;
        *(__nv_bfloat162*)(Pl + o) = lp;
    }
}

__global__ void router_kernel(const float* __restrict__ x,
                              const float* __restrict__ Wr,
                              const float* __restrict__ br) {
    int warp = (blockIdx.x * blockDim.x + threadIdx.x) >> 5;
    int lane = threadIdx.x & 31;
    if (warp >= N_TOK) return;
    const float* xr = x + (size_t)warp * D_DIM;
    float acc[8];
#pragma unroll
    for (int e = 0; e < 8; e++) acc[e] = 0.0f;
    for (int d = lane; d < D_DIM; d += 32) {
        float xv = xr[d];
        const float4* w4 = (const float4*)(Wr + (size_t)d * E_NUM);
        float4 a = w4[0], b = w4[1];
        acc[0] += xv * a.x; acc[1] += xv * a.y; acc[2] += xv * a.z; acc[3] += xv * a.w;
        acc[4] += xv * b.x; acc[5] += xv * b.y; acc[6] += xv * b.z; acc[7] += xv * b.w;
    }
#pragma unroll
    for (int off = 16; off > 0; off >>= 1)
#pragma unroll
        for (int e = 0; e < 8; e++)
            acc[e] += __shfl_down_sync(0xffffffffu, acc[e], off);
    if (lane == 0) {
        float lg[8];
#pragma unroll
        for (int e = 0; e < 8; e++) lg[e] = acc[e] + br[e];
        int e0 = 0;
#pragma unroll
        for (int e = 1; e < 8; e++) if (lg[e] > lg[e0]) e0 = e;
        int e1 = (e0 == 0) ? 1 : 0;
#pragma unroll
        for (int e = 0; e < 8; e++)
            if (e != e0 && e != e1 && lg[e] > lg[e1]) e1 = e;
        float z  = __expf(lg[e1] - lg[e0]);
        float w0 = 1.0f / (1.0f + z);
        float w1 = z * w0;
        int p0 = atomicAdd(&g_cnt[e0], 1);
        g_tok[e0 * CAP + p0] = warp;
        int p1 = atomicAdd(&g_cnt[e1], 1);
        g_tok[e1 * CAP + p1] = warp;
        g_tslot[2 * warp]     = e0 * CAP + p0;  g_tw[2 * warp]     = w0;
        g_tslot[2 * warp + 1] = e1 * CAP + p1;  g_tw[2 * warp + 1] = w1;
    }
}

__global__ void offsets_kernel() {
    if (threadIdx.x == 0 && blockIdx.x == 0) {
        int acc = 0;
#pragma unroll
        for (int e = 0; e < E_NUM; e++) { g_off[e] = acc; acc += g_cnt[e]; }
    }
}

// out[t] = w0 * y[slot0] + w1 * y[slot1]   (deterministic 2-way combine)
__global__ void combine_kernel(float* __restrict__ out) {
    int i = blockIdx.x * blockDim.x + threadIdx.x;   // 0 .. N_TOK*256-1
    int t = i >> 8;
    int j = (i & 255) << 2;
    int s0e = g_tslot[2 * t], s1e = g_tslot[2 * t + 1];
    float w0 = g_tw[2 * t], w1 = g_tw[2 * t + 1];
    size_t s0 = (size_t)g_off[s0e >> 13] + (s0e & (CAP - 1));
    size_t s1 = (size_t)g_off[s1e >> 13] + (s1e & (CAP - 1));
    float4 a = *(const float4*)(g_y + s0 * D_DIM + j);
    float4 b = *(const float4*)(g_y + s1 * D_DIM + j);
    float4 o;
    o.x = w0 * a.x + w1 * b.x;
    o.y = w0 * a.y + w1 * b.y;
    o.z = w0 * a.z + w1 * b.z;
    o.w = w0 * a.w + w1 * b.w;
    *(float4*)(out + (size_t)t * D_DIM + j) = o;
}

// -------- grouped GEMM via mma.sync (HMMA), bf16x3, 128x256 tile, 64x64 warps ------
template <int PHASE, int KDIM, int NDIM>
__global__ __launch_bounds__(256, 1)
void moe_hmma(const __nv_bfloat16* __restrict__ Ahg, const __nv_bfloat16* __restrict__ Alg,
              const __nv_bfloat16* __restrict__ Bhg, const __nv_bfloat16* __restrict__ Blg,
              const float* __restrict__ bias) {
    constexpr int C = KDIM / TK;
    const int e  = blockIdx.z;
    const int Ne = g_cnt[e];
    const int m0 = blockIdx.x * TM;
    if (m0 >= Ne) return;
    const int n0 = blockIdx.y * TN;
    const int base = g_off[e];

    extern __shared__ __align__(128) char smem[];
    const uint32_t sb = smem_u32(smem);
    const int tid = threadIdx.x;

    // ---- load assignments: thread -> row group (tid>>2), 16B seg (tid&3) ----
    const int r0 = tid >> 2;            // 0..63
    const int sg = (tid & 3) * 16;
    const char *a0h, *a0l, *a1h, *a1l;
    {
        int rr0 = min(m0 + r0, Ne - 1);
        int rr1 = min(m0 + r0 + 64, Ne - 1);
        size_t i0 = (PHASE == 1) ? (size_t)g_tok[e * CAP + rr0] : (size_t)(base + rr0);
        size_t i1 = (PHASE == 1) ? (size_t)g_tok[e * CAP + rr1] : (size_t)(base + rr1);
        a0h = (const char*)(Ahg + i0 * KDIM) + sg;
        a0l = (const char*)(Alg + i0 * KDIM) + sg;
        a1h = (const char*)(Ahg + i1 * KDIM) + sg;
        a1l = (const char*)(Alg + i1 * KDIM) + sg;
    }
    // B: 256 rows, 4 row-groups per thread
    const size_t brow = (size_t)e * NDIM + n0 + r0;
    const char* bh0 = (const char*)(Bhg + brow * KDIM) + sg;
    const char* bl0 = (const char*)(Blg + brow * KDIM) + sg;
    const uint32_t d0 = (uint32_t)r0 * ROWB + sg;

    auto issue = [&](int c) {
        if (c < C) {
            uint32_t st = sb + (uint32_t)(c % NSTAGE) * STG;
            int cb = c * 64;   // bytes per chunk along K
            CP16(st + AH + d0,             a0h + cb);
            CP16(st + AH + d0 + 64 * ROWB, a1h + cb);
            CP16(st + AL + d0,             a0l + cb);
            CP16(st + AL + d0 + 64 * ROWB, a1l + cb);
#pragma unroll
            for (int j = 0; j < 4; j++) {
                CP16(st + BH + d0 + j * 64 * ROWB, bh0 + (size_t)j * 64 * KDIM * 2 + cb);
                CP16(st + BL + d0 + j * 64 * ROWB, bl0 + (size_t)j * 64 * KDIM * 2 + cb);
            }
        }
        CP_COMMIT();
    };

    float acc[4][8][4];
#pragma unroll
    for (int i = 0; i < 4; i++)
#pragma unroll
        for (int j = 0; j < 8; j++)
#pragma unroll
            for (int k = 0; k < 4; k++) acc[i][j][k] = 0.0f;

    const int lane = tid & 31, wid = tid >> 5;
    const int wm = (wid & 1) * 64;        // warp M offset
    const int wn = (wid >> 1) * 64;       // warp N offset
    const uint32_t a_off = (uint32_t)(wm + (lane & 15)) * ROWB + (lane >> 4) * 16;
    const uint32_t b_off = (uint32_t)(wn + (lane & 7) + ((lane >> 4) & 1) * 8) * ROWB
                         + ((lane >> 3) & 1) * 16;

    issue(0);
    issue(1);

    for (int c = 0; c < C; c++) {
        asm volatile("cp.async.wait_group 1;" ::: "memory");
        __syncthreads();
        issue(c + 2);

        const uint32_t st = sb + (uint32_t)(c % NSTAGE) * STG;
#pragma unroll
        for (int kk = 0; kk < 2; kk++) {
            uint32_t af[16], tf[16];
            // A hi + B hi -> hi*hi
#pragma unroll
            for (int tm = 0; tm < 4; tm++)
                ldsm4(af + tm * 4, st + AH + a_off + tm * 16 * ROWB + kk * 32);
#pragma unroll
            for (int tn2 = 0; tn2 < 4; tn2++)
                ldsm4(tf + tn2 * 4, st + BH + b_off + tn2 * 16 * ROWB + kk * 32);
#pragma unroll
            for (int tm = 0; tm < 4; tm++)
#pragma unroll
                for (int tn = 0; tn < 8; tn++)
                    mma_bf16(acc[tm][tn], af + tm * 4, tf + tn * 2);
            // A lo x B hi
            {
                uint32_t lf[16];
#pragma unroll
                for (int tm = 0; tm < 4; tm++)
                    ldsm4(lf + tm * 4, st + AL + a_off + tm * 16 * ROWB + kk * 32);
#pragma unroll
                for (int tm = 0; tm < 4; tm++)
#pragma unroll
                    for (int tn = 0; tn < 8; tn++)
                        mma_bf16(acc[tm][tn], lf + tm * 4, tf + tn * 2);
            }
            // A hi x B lo (reuse tf)
#pragma unroll
            for (int tn2 = 0; tn2 < 4; tn2++)
                ldsm4(tf + tn2 * 4, st + BL + b_off + tn2 * 16 * ROWB + kk * 32);
#pragma unroll
            for (int tm = 0; tm < 4; tm++)
#pragma unroll
                for (int tn = 0; tn < 8; tn++)
                    mma_bf16(acc[tm][tn], af + tm * 4, tf + tn * 2);
        }
    }

    // ---- epilogue ----
    const int lr_base  = wm + (lane >> 2);
    const int col_base = n0 + wn + 2 * (lane & 3);
    const float* bp = bias + (size_t)e * NDIM;
#pragma unroll
    for (int tm = 0; tm < 4; tm++) {
#pragma unroll
        for (int half = 0; half < 2; half++) {
            int gr = m0 + lr_base + tm * 16 + half * 8;
            if (gr < Ne) {
                size_t pr = (size_t)(base + gr);
#pragma unroll
                for (int tn = 0; tn < 8; tn++) {
                    int col = col_base + tn * 8;
                    float c0 = acc[tm][tn][half * 2 + 0] + __ldg(bp + col);
                    float c1 = acc[tm][tn][half * 2 + 1] + __ldg(bp + col + 1);
                    if (PHASE == 1) {
                        c0 = fmaxf(c0, 0.f);
                        c1 = fmaxf(c1, 0.f);
                        __nv_bfloat16 h0 = __float2bfloat16(c0);
                        __nv_bfloat16 h1 = __float2bfloat16(c1);
                        __nv_bfloat162 hp; hp.x = h0; hp.y = h1;
                        __nv_bfloat162 lp;
                        lp.x = __float2bfloat16(c0 - __bfloat162float(h0));
                        lp.y = __float2bfloat16(c1 - __bfloat162float(h1));
                        *(__nv_bfloat162*)(g_hh + pr * H_DIM + col) = hp;
                        *(__nv_bfloat162*)(g_hl + pr * H_DIM + col) = lp;
                    } else {
                        float2 o; o.x = c0; o.y = c1;
                        *(float2*)(g_y + pr * D_DIM + col) = o;
                    }
                }
            }
        }
    }
}

// ---------------- launch ----------------
extern "C" void kernel_launch(void* const* d_in, const int* in_sizes, int n_in,
                              void* d_out, int out_size) {
    const float* x  = (const float*)d_in[0];
    const float* Wr = (const float*)d_in[1];
    const float* br = (const float*)d_in[2];
    const float* W1 = (const float*)d_in[3];
    const float* b1 = (const float*)d_in[4];
    const float* W2 = (const float*)d_in[5];
    const float* b2 = (const float*)d_in[6];
    float* out = (float*)d_out;

    cudaFuncSetAttribute(moe_hmma<1, D_DIM, H_DIM>,
                         cudaFuncAttributeMaxDynamicSharedMemorySize, GEMM_SMEM);
    cudaFuncSetAttribute(moe_hmma<2, H_DIM, D_DIM>,
                         cudaFuncAttributeMaxDynamicSharedMemorySize, GEMM_SMEM);

    __nv_bfloat16 *xh, *xl, *hh, *hl, *B1h, *B1l, *B2h, *B2l;
    cudaGetSymbolAddress((void**)&xh,  g_xh);  cudaGetSymbolAddress((void**)&xl,  g_xl);
    cudaGetSymbolAddress((void**)&hh,  g_hh);  cudaGetSymbolAddress((void**)&hl,  g_hl);
    cudaGetSymbolAddress((void**)&B1h, g_B1h); cudaGetSymbolAddress((void**)&B1l, g_B1l);
    cudaGetSymbolAddress((void**)&B2h, g_B2h); cudaGetSymbolAddress((void**)&B2l, g_B2l);

    zero_cnt_kernel<<<1, 32>>>();
    cvt_x_kernel<<<1024, 256>>>(x);
    {   // W1: K=1024, N=4096 -> [E][4096][1024]
        dim3 g(D_DIM / 32, H_DIM / 32, E_NUM);
        pack_w_kernel<<<g, 256>>>(W1, B1h, B1l, D_DIM, H_DIM);
    }
    {   // W2: K=4096, N=1024 -> [E][1024][4096]
        dim3 g(H_DIM / 32, D_DIM / 32, E_NUM);
        pack_w_kernel<<<g, 256>>>(W2, B2h, B2l, H_DIM, D_DIM);
    }
    router_kernel<<<(N_TOK * 32 + 255) / 256, 256>>>(x, Wr, br);
    offsets_kernel<<<1, 32>>>();

    {   // GEMM1: gathered x [Ne,1024] @ W1^T-packed -> relu -> h (hi/lo)
        dim3 g(CAP / TM, H_DIM / TN, E_NUM);
        moe_hmma<1, D_DIM, H_DIM><<<g, 256, GEMM_SMEM>>>(xh, xl, B1h, B1l, b1);
    }
    {   // GEMM2: h [Ne,4096] @ W2^T-packed -> y (+b2)
        dim3 g(CAP / TM, D_DIM / TN, E_NUM);
        moe_hmma<2, H_DIM, D_DIM><<<g, 256, GEMM_SMEM>>>(hh, hl, B2h, B2l, b2);
    }
    combine_kernel<<<N_TOK, 256>>>(out);
}

// round 7
// speedup vs baseline: 3.7739x; 1.3935x over previous
#include <cuda_runtime.h>
#include <cuda_fp16.h>
#include <math.h>
#include <stdint.h>

#define N_TOK 8192
#define D_DIM 1024
#define E_NUM 8
#define H_DIM 4096
#define CAP   8192
#define PAIRS 16384

#define TM 128
#define TN 256
#define TK 32            // fp16 elems per k-chunk (64 bytes per row)
#define ROWB 80          // padded SMEM row bytes (64 data + 16 pad)
#define AH 0
#define AL 10240
#define BH 20480
#define STG 40960
#define NSTAGE 3
#define GEMM_SMEM (NSTAGE * STG)

// ---------------- device scratch ----------------
__device__ int   g_cnt[E_NUM];
__device__ int   g_off[E_NUM];
__device__ int   g_tok[E_NUM * CAP];
__device__ int   g_tslot[2 * N_TOK];   // e*CAP + p for each token's 2 experts
__device__ float g_tw  [2 * N_TOK];

__device__ __half g_xh[(size_t)N_TOK * D_DIM];
__device__ __half g_xl[(size_t)N_TOK * D_DIM];
__device__ __half g_hh[(size_t)PAIRS * H_DIM];
__device__ __half g_hl[(size_t)PAIRS * H_DIM];
__device__ float  g_y [(size_t)PAIRS * D_DIM];
// packed weights (hi only), [E][N][K] row-major fp16
__device__ __half g_B1h[(size_t)E_NUM * H_DIM * D_DIM];
__device__ __half g_B2h[(size_t)E_NUM * D_DIM * H_DIM];

// ---------------- helpers ----------------
__device__ __forceinline__ uint32_t smem_u32(const void* p) {
    return (uint32_t)__cvta_generic_to_shared(p);
}
#define CP16(dst, src) \
    asm volatile("cp.async.cg.shared.global [%0], [%1], 16;" :: "r"(dst), "l"(src) : "memory")
#define CP_COMMIT() asm volatile("cp.async.commit_group;" ::: "memory")

__device__ __forceinline__ void ldsm4(uint32_t* r, uint32_t addr) {
    asm volatile("ldmatrix.sync.aligned.m8n8.x4.shared.b16 {%0,%1,%2,%3}, [%4];"
        : "=r"(r[0]), "=r"(r[1]), "=r"(r[2]), "=r"(r[3]) : "r"(addr));
}
__device__ __forceinline__ void mma_f16(float* c, const uint32_t* a, const uint32_t* b) {
    asm volatile("mma.sync.aligned.m16n8k16.row.col.f32.f16.f16.f32 "
        "{%0,%1,%2,%3}, {%4,%5,%6,%7}, {%8,%9}, {%0,%1,%2,%3};"
        : "+f"(c[0]), "+f"(c[1]), "+f"(c[2]), "+f"(c[3])
        : "r"(a[0]), "r"(a[1]), "r"(a[2]), "r"(a[3]), "r"(b[0]), "r"(b[1]));
}

// ---------------- small kernels ----------------
__global__ void zero_cnt_kernel() {
    if (threadIdx.x < E_NUM) g_cnt[threadIdx.x] = 0;
}

__global__ void cvt_x_kernel(const float* __restrict__ x) {
    size_t stride = (size_t)gridDim.x * blockDim.x;
    size_t n = (size_t)N_TOK * D_DIM;
    for (size_t i = (size_t)blockIdx.x * blockDim.x + threadIdx.x; i < n; i += stride) {
        float v = x[i];
        __half h = __float2half_rn(v);
        g_xh[i] = h;
        g_xl[i] = __float2half_rn(v - __half2float(h));
    }
}

// W[e][K][N] fp32 -> P[e][N][K] fp16 hi (32x32 tile transpose)
__global__ __launch_bounds__(256)
void pack_w_kernel(const float* __restrict__ W, __half* __restrict__ Ph, int K, int N) {
    __shared__ float s[32][33];
    const int k0 = blockIdx.x * 32, n0 = blockIdx.y * 32, e = blockIdx.z;
    const int tid = threadIdx.x;
    const int kk = tid >> 5, nn = tid & 31;
#pragma unroll
    for (int i = 0; i < 4; i++)
        s[kk + i * 8][nn] = W[((size_t)e * K + k0 + kk + i * 8) * N + n0 + nn];
    __syncthreads();
    const int n_r = tid >> 4;          // 0..15
    const int kp  = (tid & 15) * 2;
#pragma unroll
    for (int i = 0; i < 2; i++) {
        int nr = n_r + i * 16;
        __half2 hp;
        hp.x = __float2half_rn(s[kp][nr]);
        hp.y = __float2half_rn(s[kp + 1][nr]);
        size_t o = ((size_t)e * N + n0 + nr) * K + k0 + kp;
        *(__half2*)(Ph + o) = hp;
    }
}

__global__ void router_kernel(const float* __restrict__ x,
                              const float* __restrict__ Wr,
                              const float* __restrict__ br) {
    int warp = (blockIdx.x * blockDim.x + threadIdx.x) >> 5;
    int lane = threadIdx.x & 31;
    if (warp >= N_TOK) return;
    const float* xr = x + (size_t)warp * D_DIM;
    float acc[8];
#pragma unroll
    for (int e = 0; e < 8; e++) acc[e] = 0.0f;
    for (int d = lane; d < D_DIM; d += 32) {
        float xv = xr[d];
        const float4* w4 = (const float4*)(Wr + (size_t)d * E_NUM);
        float4 a = w4[0], b = w4[1];
        acc[0] += xv * a.x; acc[1] += xv * a.y; acc[2] += xv * a.z; acc[3] += xv * a.w;
        acc[4] += xv * b.x; acc[5] += xv * b.y; acc[6] += xv * b.z; acc[7] += xv * b.w;
    }
#pragma unroll
    for (int off = 16; off > 0; off >>= 1)
#pragma unroll
        for (int e = 0; e < 8; e++)
            acc[e] += __shfl_down_sync(0xffffffffu, acc[e], off);
    if (lane == 0) {
        float lg[8];
#pragma unroll
        for (int e = 0; e < 8; e++) lg[e] = acc[e] + br[e];
        int e0 = 0;
#pragma unroll
        for (int e = 1; e < 8; e++) if (lg[e] > lg[e0]) e0 = e;
        int e1 = (e0 == 0) ? 1 : 0;
#pragma unroll
        for (int e = 0; e < 8; e++)
            if (e != e0 && e != e1 && lg[e] > lg[e1]) e1 = e;
        float z  = __expf(lg[e1] - lg[e0]);
        float w0 = 1.0f / (1.0f + z);
        float w1 = z * w0;
        int p0 = atomicAdd(&g_cnt[e0], 1);
        g_tok[e0 * CAP + p0] = warp;
        int p1 = atomicAdd(&g_cnt[e1], 1);
        g_tok[e1 * CAP + p1] = warp;
        g_tslot[2 * warp]     = e0 * CAP + p0;  g_tw[2 * warp]     = w0;
        g_tslot[2 * warp + 1] = e1 * CAP + p1;  g_tw[2 * warp + 1] = w1;
    }
}

__global__ void offsets_kernel() {
    if (threadIdx.x == 0 && blockIdx.x == 0) {
        int acc = 0;
#pragma unroll
        for (int e = 0; e < E_NUM; e++) { g_off[e] = acc; acc += g_cnt[e]; }
    }
}

// out[t] = w0 * y[slot0] + w1 * y[slot1]   (deterministic 2-way combine)
__global__ void combine_kernel(float* __restrict__ out) {
    int i = blockIdx.x * blockDim.x + threadIdx.x;   // 0 .. N_TOK*256-1
    int t = i >> 8;
    int j = (i & 255) << 2;
    int s0e = g_tslot[2 * t], s1e = g_tslot[2 * t + 1];
    float w0 = g_tw[2 * t], w1 = g_tw[2 * t + 1];
    size_t s0 = (size_t)g_off[s0e >> 13] + (s0e & (CAP - 1));
    size_t s1 = (size_t)g_off[s1e >> 13] + (s1e & (CAP - 1));
    float4 a = *(const float4*)(g_y + s0 * D_DIM + j);
    float4 b = *(const float4*)(g_y + s1 * D_DIM + j);
    float4 o;
    o.x = w0 * a.x + w1 * b.x;
    o.y = w0 * a.y + w1 * b.y;
    o.z = w0 * a.z + w1 * b.z;
    o.w = w0 * a.w + w1 * b.w;
    *(float4*)(out + (size_t)t * D_DIM + j) = o;
}

// ---- grouped GEMM via mma.sync fp16, 2-term split, 128x256 tile, 64x64 warps ----
template <int PHASE, int KDIM, int NDIM>
__global__ __launch_bounds__(256, 1)
void moe_hmma(const __half* __restrict__ Ahg, const __half* __restrict__ Alg,
              const __half* __restrict__ Bhg,
              const float* __restrict__ bias) {
    constexpr int C = KDIM / TK;
    const int e  = blockIdx.z;
    const int Ne = g_cnt[e];
    const int m0 = blockIdx.x * TM;
    if (m0 >= Ne) return;
    const int n0 = blockIdx.y * TN;
    const int base = g_off[e];

    extern __shared__ __align__(128) char smem[];
    const uint32_t sb = smem_u32(smem);
    const int tid = threadIdx.x;

    // ---- load assignments: thread -> row group (tid>>2), 16B seg (tid&3) ----
    const int r0 = tid >> 2;            // 0..63
    const int sg = (tid & 3) * 16;
    const char *a0h, *a0l, *a1h, *a1l;
    {
        int rr0 = min(m0 + r0, Ne - 1);
        int rr1 = min(m0 + r0 + 64, Ne - 1);
        size_t i0 = (PHASE == 1) ? (size_t)g_tok[e * CAP + rr0] : (size_t)(base + rr0);
        size_t i1 = (PHASE == 1) ? (size_t)g_tok[e * CAP + rr1] : (size_t)(base + rr1);
        a0h = (const char*)(Ahg + i0 * KDIM) + sg;
        a0l = (const char*)(Alg + i0 * KDIM) + sg;
        a1h = (const char*)(Ahg + i1 * KDIM) + sg;
        a1l = (const char*)(Alg + i1 * KDIM) + sg;
    }
    // B: 256 rows, 4 row-groups per thread (hi only)
    const size_t brow = (size_t)e * NDIM + n0 + r0;
    const char* bh0 = (const char*)(Bhg + brow * KDIM) + sg;
    const uint32_t d0 = (uint32_t)r0 * ROWB + sg;

    auto issue = [&](int c) {
        if (c < C) {
            uint32_t st = sb + (uint32_t)(c % NSTAGE) * STG;
            int cb = c * 64;   // bytes per chunk along K
            CP16(st + AH + d0,             a0h + cb);
            CP16(st + AH + d0 + 64 * ROWB, a1h + cb);
            CP16(st + AL + d0,             a0l + cb);
            CP16(st + AL + d0 + 64 * ROWB, a1l + cb);
#pragma unroll
            for (int j = 0; j < 4; j++)
                CP16(st + BH + d0 + j * 64 * ROWB, bh0 + (size_t)j * 64 * KDIM * 2 + cb);
        }
        CP_COMMIT();
    };

    float acc[4][8][4];
#pragma unroll
    for (int i = 0; i < 4; i++)
#pragma unroll
        for (int j = 0; j < 8; j++)
#pragma unroll
            for (int k = 0; k < 4; k++) acc[i][j][k] = 0.0f;

    const int lane = tid & 31, wid = tid >> 5;
    const int wm = (wid & 1) * 64;        // warp M offset
    const int wn = (wid >> 1) * 64;       // warp N offset
    const uint32_t a_off = (uint32_t)(wm + (lane & 15)) * ROWB + (lane >> 4) * 16;
    const uint32_t b_off = (uint32_t)(wn + (lane & 7) + ((lane >> 4) & 1) * 8) * ROWB
                         + ((lane >> 3) & 1) * 16;

    issue(0);
    issue(1);

    for (int c = 0; c < C; c++) {
        asm volatile("cp.async.wait_group 1;" ::: "memory");
        __syncthreads();
        issue(c + 2);

        const uint32_t st = sb + (uint32_t)(c % NSTAGE) * STG;
#pragma unroll
        for (int kk = 0; kk < 2; kk++) {
            uint32_t af[16], tf[16];
            // B hi fragments (shared by both terms)
#pragma unroll
            for (int tn2 = 0; tn2 < 4; tn2++)
                ldsm4(tf + tn2 * 4, st + BH + b_off + tn2 * 16 * ROWB + kk * 32);
            // A hi x B hi
#pragma unroll
            for (int tm = 0; tm < 4; tm++)
                ldsm4(af + tm * 4, st + AH + a_off + tm * 16 * ROWB + kk * 32);
#pragma unroll
            for (int tm = 0; tm < 4; tm++)
#pragma unroll
                for (int tn = 0; tn < 8; tn++)
                    mma_f16(acc[tm][tn], af + tm * 4, tf + tn * 2);
            // A lo x B hi (reuse af)
#pragma unroll
            for (int tm = 0; tm < 4; tm++)
                ldsm4(af + tm * 4, st + AL + a_off + tm * 16 * ROWB + kk * 32);
#pragma unroll
            for (int tm = 0; tm < 4; tm++)
#pragma unroll
                for (int tn = 0; tn < 8; tn++)
                    mma_f16(acc[tm][tn], af + tm * 4, tf + tn * 2);
        }
    }

    // ---- epilogue ----
    const int lr_base  = wm + (lane >> 2);
    const int col_base = n0 + wn + 2 * (lane & 3);
    const float* bp = bias + (size_t)e * NDIM;
#pragma unroll
    for (int tm = 0; tm < 4; tm++) {
#pragma unroll
        for (int half = 0; half < 2; half++) {
            int gr = m0 + lr_base + tm * 16 + half * 8;
            if (gr < Ne) {
                size_t pr = (size_t)(base + gr);
#pragma unroll
                for (int tn = 0; tn < 8; tn++) {
                    int col = col_base + tn * 8;
                    float c0 = acc[tm][tn][half * 2 + 0] + __ldg(bp + col);
                    float c1 = acc[tm][tn][half * 2 + 1] + __ldg(bp + col + 1);
                    if (PHASE == 1) {
                        c0 = fmaxf(c0, 0.f);
                        c1 = fmaxf(c1, 0.f);
                        __half h0 = __float2half_rn(c0);
                        __half h1 = __float2half_rn(c1);
                        __half2 hp; hp.x = h0; hp.y = h1;
                        __half2 lp;
                        lp.x = __float2half_rn(c0 - __half2float(h0));
                        lp.y = __float2half_rn(c1 - __half2float(h1));
                        *(__half2*)(g_hh + pr * H_DIM + col) = hp;
                        *(__half2*)(g_hl + pr * H_DIM + col) = lp;
                    } else {
                        float2 o; o.x = c0; o.y = c1;
                        *(float2*)(g_y + pr * D_DIM + col) = o;
                    }
                }
            }
        }
    }
}

// ---------------- launch ----------------
extern "C" void kernel_launch(void* const* d_in, const int* in_sizes, int n_in,
                              void* d_out, int out_size) {
    const float* x  = (const float*)d_in[0];
    const float* Wr = (const float*)d_in[1];
    const float* br = (const float*)d_in[2];
    const float* W1 = (const float*)d_in[3];
    const float* b1 = (const float*)d_in[4];
    const float* W2 = (const float*)d_in[5];
    const float* b2 = (const float*)d_in[6];
    float* out = (float*)d_out;

    cudaFuncSetAttribute(moe_hmma<1, D_DIM, H_DIM>,
                         cudaFuncAttributeMaxDynamicSharedMemorySize, GEMM_SMEM);
    cudaFuncSetAttribute(moe_hmma<2, H_DIM, D_DIM>,
                         cudaFuncAttributeMaxDynamicSharedMemorySize, GEMM_SMEM);

    __half *xh, *xl, *hh, *hl, *B1h, *B2h;
    cudaGetSymbolAddress((void**)&xh,  g_xh);  cudaGetSymbolAddress((void**)&xl,  g_xl);
    cudaGetSymbolAddress((void**)&hh,  g_hh);  cudaGetSymbolAddress((void**)&hl,  g_hl);
    cudaGetSymbolAddress((void**)&B1h, g_B1h); cudaGetSymbolAddress((void**)&B2h, g_B2h);

    zero_cnt_kernel<<<1, 32>>>();
    cvt_x_kernel<<<1024, 256>>>(x);
    {   // W1: K=1024, N=4096 -> [E][4096][1024]
        dim3 g(D_DIM / 32, H_DIM / 32, E_NUM);
        pack_w_kernel<<<g, 256>>>(W1, B1h, D_DIM, H_DIM);
    }
    {   // W2: K=4096, N=1024 -> [E][1024][4096]
        dim3 g(H_DIM / 32, D_DIM / 32, E_NUM);
        pack_w_kernel<<<g, 256>>>(W2, B2h, H_DIM, D_DIM);
    }
    router_kernel<<<(N_TOK * 32 + 255) / 256, 256>>>(x, Wr, br);
    offsets_kernel<<<1, 32>>>();

    {   // GEMM1: gathered x [Ne,1024] @ W1^T-packed -> relu -> h (hi/lo fp16)
        dim3 g(CAP / TM, H_DIM / TN, E_NUM);
        moe_hmma<1, D_DIM, H_DIM><<<g, 256, GEMM_SMEM>>>(xh, xl, B1h, b1);
    }
    {   // GEMM2: h [Ne,4096] @ W2^T-packed -> y (+b2)
        dim3 g(CAP / TM, D_DIM / TN, E_NUM);
        moe_hmma<2, H_DIM, D_DIM><<<g, 256, GEMM_SMEM>>>(hh, hl, B2h, b2);
    }
    combine_kernel<<<N_TOK, 256>>>(out);
}